// round 15
// baseline (speedup 1.0000x reference)
#include <cuda_runtime.h>
#include <cstdint>

// GRU-D diagonal recurrence. One thread = one (b,f) chain, T=512 steps.
// R15: UNROLL=4, depth-3 pipeline (4 slots, period-4 rotation, x4-unrolled
// branch-free loop). Smaller/more-frequent load fronts (12 LDGs every ~320cyc)
// for smoother DRAM demand; lead ~960cyc > 577 DRAM latency. Body math and
// cache policy identical to the proven R5 kernel.

#define TT 512
#define BB 256
#define FF 256
#define BF (BB * FF)
#define UNROLL 4
#define NBATCH (TT / UNROLL)   // 128
#define BLK 64

__device__ __forceinline__ float tanh_approx(float v) {
    float r;
    asm("tanh.approx.f32 %0, %1;" : "=f"(r) : "f"(v));
    return r;
}
__device__ __forceinline__ float ex2_f(float v) {
    float r;
    asm("ex2.approx.f32 %0, %1;" : "=f"(r) : "f"(v));
    return r;
}

__global__ void __launch_bounds__(BLK) grud_kernel(
    const float* __restrict__ X,
    const float* __restrict__ Mask,
    const float* __restrict__ Delta,
    const float* __restrict__ x_mean,
    const float* __restrict__ w_dg_x, const float* __restrict__ b_dg_x,
    const float* __restrict__ w_dg_h, const float* __restrict__ b_dg_h,
    const float* __restrict__ w_xz,  const float* __restrict__ u_hz, const float* __restrict__ b_z,
    const float* __restrict__ w_xr,  const float* __restrict__ u_hr, const float* __restrict__ b_r,
    const float* __restrict__ w_xh,  const float* __restrict__ u_hh,
    const float* __restrict__ v_mh,  const float* __restrict__ b_h,
    float* __restrict__ out,        // [B, T, F]
    float* __restrict__ out_last)   // [B, F] or nullptr
{
    const int tid = blockIdx.x * BLK + threadIdx.x;
    const int f = tid & (FF - 1);
    const int b = tid >> 8;

    const float LOG2E = 1.4426950408889634f;

    const float xm    = x_mean[f];
    const float nwdgx = -LOG2E * w_dg_x[f], nbdgx = -LOG2E * b_dg_x[f];
    const float nwdgh = -LOG2E * w_dg_h[f], nbdgh = -LOG2E * b_dg_h[f];
    const float wxz2  = 0.5f * w_xz[f], uhz2 = 0.5f * u_hz[f], bz2 = 0.5f * b_z[f];
    const float wxr2  = 0.5f * w_xr[f], uhr2 = 0.5f * u_hr[f], br2 = 0.5f * b_r[f];
    const float wxh   = w_xh[f], uhh = u_hh[f];
    const float vmh   = v_mh[f], bh  = b_h[f];

    const float* xp = X     + (size_t)b * FF + f;       // [T,B,F]: t-stride BF
    const float* mp = Mask  + (size_t)b * FF + f;
    const float* dp = Delta + (size_t)b * FF + f;
    float*       op = out   + (size_t)b * TT * FF + f;  // [B,T,F]: t-stride FF

    float h = 0.0f;

    // 4 register buffers; all slot indices below are literal constants.
    float xv[4][UNROLL], mv[4][UNROLL], dv[4][UNROLL];

    auto load_batch = [&](int n, int s) {
        const float* xq = xp + (size_t)n * (BF * UNROLL);
        const float* mq = mp + (size_t)n * (BF * UNROLL);
        const float* dq = dp + (size_t)n * (BF * UNROLL);
        #pragma unroll
        for (int u = 0; u < UNROLL; ++u) {
            xv[s][u] = __ldcs(xq + u * BF);
            mv[s][u] = __ldcs(mq + u * BF);
            dv[s][u] = __ldcs(dq + u * BF);
        }
    };
    auto compute_batch = [&](int n, int s) {
        float* oq = op + (size_t)n * (FF * UNROLL);
        #pragma unroll
        for (int u = 0; u < UNROLL; ++u) {
            float x = xv[s][u], m = mv[s][u], d = dv[s][u];

            // gamma = exp(-relu(w*d+b)) = ex2(min(0, fma(nw, d, nb)))
            float gx = ex2_f(fminf(0.0f, fmaf(nwdgx, d, nbdgx)));
            float gh = ex2_f(fminf(0.0f, fmaf(nwdgh, d, nbdgh)));

            // x = m*x + (1-m)*(gx*x + (1-gx)*xm)
            float ximp = fmaf(gx, x, (1.0f - gx) * xm);
            x = fmaf(m, x, (1.0f - m) * ximp);

            float pz = fmaf(wxz2, x, bz2);
            float pr = fmaf(wxr2, x, br2);
            float ph = fmaf(wxh, x, fmaf(vmh, m, bh));

            h = gh * h;

            float z  = fmaf(0.5f, tanh_approx(fmaf(uhz2, h, pz)), 0.5f);
            float r  = fmaf(0.5f, tanh_approx(fmaf(uhr2, h, pr)), 0.5f);
            float ht = tanh_approx(fmaf(uhh, r * h, ph));

            h = fmaf(z, ht - h, h);

            __stcs(oq + u * FF, h);
        }
    };

    // Depth-3 pipeline: batches 0..2 in flight before any compute.
    load_batch(0, 0);
    load_batch(1, 1);
    load_batch(2, 2);

    // Branch-free main loop: n = 0,4,...,120 (computes 0..123, loads thru 126).
    #pragma unroll 1
    for (int n = 0; n <= NBATCH - 8; n += 4) {
        load_batch(n + 3, 3);  compute_batch(n,     0);
        load_batch(n + 4, 0);  compute_batch(n + 1, 1);
        load_batch(n + 5, 1);  compute_batch(n + 2, 2);
        load_batch(n + 6, 2);  compute_batch(n + 3, 3);
    }
    // Slots now: 124->s0, 125->s1, 126->s2.
    load_batch(NBATCH - 1, 3);
    compute_batch(NBATCH - 4, 0);
    compute_batch(NBATCH - 3, 1);
    compute_batch(NBATCH - 2, 2);
    compute_batch(NBATCH - 1, 3);

    if (out_last != nullptr) {
        out_last[(size_t)b * FF + f] = h;
    }
}

extern "C" void kernel_launch(void* const* d_in, const int* in_sizes, int n_in,
                              void* d_out, int out_size) {
    const float* X      = (const float*)d_in[0];
    const float* Mask   = (const float*)d_in[1];
    const float* Delta  = (const float*)d_in[2];
    const float* x_mean = (const float*)d_in[3];
    const float* w_dg_x = (const float*)d_in[4];
    const float* b_dg_x = (const float*)d_in[5];
    const float* w_dg_h = (const float*)d_in[6];
    const float* b_dg_h = (const float*)d_in[7];
    const float* w_xz   = (const float*)d_in[8];
    const float* u_hz   = (const float*)d_in[9];
    const float* b_z    = (const float*)d_in[10];
    const float* w_xr   = (const float*)d_in[11];
    const float* u_hr   = (const float*)d_in[12];
    const float* b_r    = (const float*)d_in[13];
    const float* w_xh   = (const float*)d_in[14];
    const float* u_hh   = (const float*)d_in[15];
    const float* v_mh   = (const float*)d_in[16];
    const float* b_h    = (const float*)d_in[17];

    float* out = (float*)d_out;
    const long long hs_elems = (long long)BB * TT * FF;
    float* out_last = ((long long)out_size >= hs_elems + (long long)BB * FF)
                          ? out + hs_elems : nullptr;

    grud_kernel<<<BF / BLK, BLK>>>(X, Mask, Delta, x_mean,
                                   w_dg_x, b_dg_x, w_dg_h, b_dg_h,
                                   w_xz, u_hz, b_z,
                                   w_xr, u_hr, b_r,
                                   w_xh, u_hh, v_mh, b_h,
                                   out, out_last);
}

// round 16
// speedup vs baseline: 1.0538x; 1.0538x over previous
#include <cuda_runtime.h>
#include <cstdint>

// GRU-D diagonal recurrence. One thread = one (b,f) chain, T=512 steps.
// FINAL (== R5, best measured: 91.9us, reconfirmed 92.2us):
//   - depth-2 software pipeline, period-3 slot rotation via x3-unrolled loop
//   - batch-front .cs loads with compile-time immediate offsets (UNROLL=8)
//   - ex2-folded gammas: exp(-relu(w*d+b)) = ex2(min(0, fma(-log2e*w, d, -log2e*b)))
//   - sigmoid via 0.5*tanh(0.5v)+0.5 with pre-halved weights (1 MUFU each)
//   - .cs streaming stores (evict-first; keeps L2 clean across graph replays)
// Inputs are [T,B,F] (t-stride BF); output is [B,T,F] (t-stride FF).
// ~94% of the effective LTS/DRAM ceiling for this 3-read/1-write mix.

#define TT 512
#define BB 256
#define FF 256
#define BF (BB * FF)
#define UNROLL 8
#define NBATCH (TT / UNROLL)   // 64
#define BLK 64

__device__ __forceinline__ float tanh_approx(float v) {
    float r;
    asm("tanh.approx.f32 %0, %1;" : "=f"(r) : "f"(v));
    return r;
}
__device__ __forceinline__ float ex2_f(float v) {
    float r;
    asm("ex2.approx.f32 %0, %1;" : "=f"(r) : "f"(v));
    return r;
}

__global__ void __launch_bounds__(BLK) grud_kernel(
    const float* __restrict__ X,
    const float* __restrict__ Mask,
    const float* __restrict__ Delta,
    const float* __restrict__ x_mean,
    const float* __restrict__ w_dg_x, const float* __restrict__ b_dg_x,
    const float* __restrict__ w_dg_h, const float* __restrict__ b_dg_h,
    const float* __restrict__ w_xz,  const float* __restrict__ u_hz, const float* __restrict__ b_z,
    const float* __restrict__ w_xr,  const float* __restrict__ u_hr, const float* __restrict__ b_r,
    const float* __restrict__ w_xh,  const float* __restrict__ u_hh,
    const float* __restrict__ v_mh,  const float* __restrict__ b_h,
    float* __restrict__ out,        // [B, T, F]
    float* __restrict__ out_last)   // [B, F] or nullptr
{
    const int tid = blockIdx.x * BLK + threadIdx.x;
    const int f = tid & (FF - 1);
    const int b = tid >> 8;

    const float LOG2E = 1.4426950408889634f;

    // Per-feature params with constants folded in.
    const float xm    = x_mean[f];
    const float nwdgx = -LOG2E * w_dg_x[f], nbdgx = -LOG2E * b_dg_x[f];
    const float nwdgh = -LOG2E * w_dg_h[f], nbdgh = -LOG2E * b_dg_h[f];
    const float wxz2  = 0.5f * w_xz[f], uhz2 = 0.5f * u_hz[f], bz2 = 0.5f * b_z[f];
    const float wxr2  = 0.5f * w_xr[f], uhr2 = 0.5f * u_hr[f], br2 = 0.5f * b_r[f];
    const float wxh   = w_xh[f], uhh = u_hh[f];
    const float vmh   = v_mh[f], bh  = b_h[f];

    const float* xp = X     + (size_t)b * FF + f;   // [T,B,F]: t-stride = BF
    const float* mp = Mask  + (size_t)b * FF + f;
    const float* dp = Delta + (size_t)b * FF + f;
    float*       op = out   + (size_t)b * TT * FF + f;  // [B,T,F]: t-stride = FF

    float h = 0.0f;

    // 3 register buffers; all slot indices below are literal constants.
    float xv[3][UNROLL], mv[3][UNROLL], dv[3][UNROLL];

    auto load_batch = [&](int n, int s) {
        const float* xq = xp + (size_t)n * (BF * UNROLL);
        const float* mq = mp + (size_t)n * (BF * UNROLL);
        const float* dq = dp + (size_t)n * (BF * UNROLL);
        #pragma unroll
        for (int u = 0; u < UNROLL; ++u) {
            xv[s][u] = __ldcs(xq + u * BF);
            mv[s][u] = __ldcs(mq + u * BF);
            dv[s][u] = __ldcs(dq + u * BF);
        }
    };
    auto compute_batch = [&](int n, int s) {
        float* oq = op + (size_t)n * (FF * UNROLL);   // OUTPUT stride: FF per t
        #pragma unroll
        for (int u = 0; u < UNROLL; ++u) {
            float x = xv[s][u], m = mv[s][u], d = dv[s][u];

            // gamma = exp(-relu(w*d+b)) = ex2(min(0, fma(nw, d, nb)))
            float gx = ex2_f(fminf(0.0f, fmaf(nwdgx, d, nbdgx)));
            float gh = ex2_f(fminf(0.0f, fmaf(nwdgh, d, nbdgh)));

            // x = m*x + (1-m)*(gx*x + (1-gx)*xm)
            float ximp = fmaf(gx, x, (1.0f - gx) * xm);
            x = fmaf(m, x, (1.0f - m) * ximp);

            // h-independent partials (fill load shadow)
            float pz = fmaf(wxz2, x, bz2);
            float pr = fmaf(wxr2, x, br2);
            float ph = fmaf(wxh, x, fmaf(vmh, m, bh));

            h = gh * h;

            float z  = fmaf(0.5f, tanh_approx(fmaf(uhz2, h, pz)), 0.5f);
            float r  = fmaf(0.5f, tanh_approx(fmaf(uhr2, h, pr)), 0.5f);
            float ht = tanh_approx(fmaf(uhh, r * h, ph));

            h = fmaf(z, ht - h, h);

            __stcs(oq + u * FF, h);                   // streaming store
        }
    };

    // Depth-2 pipeline, period-3 slot rotation via x3-unrolled loop.
    load_batch(0, 0);
    load_batch(1, 1);

    #pragma unroll 1
    for (int n = 0; n < NBATCH - 1; n += 3) {
        load_batch(n + 2, 2);
        compute_batch(n, 0);                        // slot0 free
        if (n + 3 < NBATCH) load_batch(n + 3, 0);
        compute_batch(n + 1, 1);                    // slot1 free
        if (n + 4 < NBATCH) load_batch(n + 4, 1);
        compute_batch(n + 2, 2);                    // slot2 free
    }
    // Batch 63 was loaded into slot0 during the n=60 iteration.
    compute_batch(NBATCH - 1, 0);

    if (out_last != nullptr) {
        out_last[(size_t)b * FF + f] = h;
    }
}

extern "C" void kernel_launch(void* const* d_in, const int* in_sizes, int n_in,
                              void* d_out, int out_size) {
    const float* X      = (const float*)d_in[0];
    const float* Mask   = (const float*)d_in[1];
    const float* Delta  = (const float*)d_in[2];
    const float* x_mean = (const float*)d_in[3];
    const float* w_dg_x = (const float*)d_in[4];
    const float* b_dg_x = (const float*)d_in[5];
    const float* w_dg_h = (const float*)d_in[6];
    const float* b_dg_h = (const float*)d_in[7];
    const float* w_xz   = (const float*)d_in[8];
    const float* u_hz   = (const float*)d_in[9];
    const float* b_z    = (const float*)d_in[10];
    const float* w_xr   = (const float*)d_in[11];
    const float* u_hr   = (const float*)d_in[12];
    const float* b_r    = (const float*)d_in[13];
    const float* w_xh   = (const float*)d_in[14];
    const float* u_hh   = (const float*)d_in[15];
    const float* v_mh   = (const float*)d_in[16];
    const float* b_h    = (const float*)d_in[17];

    float* out = (float*)d_out;
    const long long hs_elems = (long long)BB * TT * FF;
    float* out_last = ((long long)out_size >= hs_elems + (long long)BB * FF)
                          ? out + hs_elems : nullptr;

    grud_kernel<<<BF / BLK, BLK>>>(X, Mask, Delta, x_mean,
                                   w_dg_x, b_dg_x, w_dg_h, b_dg_h,
                                   w_xz, u_hz, b_z,
                                   w_xr, u_hr, b_r,
                                   w_xh, u_hh, v_mh, b_h,
                                   out, out_last);
}

// round 17
// speedup vs baseline: 1.0564x; 1.0024x over previous
#include <cuda_runtime.h>
#include <cstdint>

// GRU-D diagonal recurrence. One thread = one (b,f) chain, T=512 steps.
// FINAL (best measured: 91.9us; reconfirmed 92.2 / 92.1us):
//   - depth-2 software pipeline, period-3 slot rotation via x3-unrolled loop
//   - batch-front .cs loads with compile-time immediate offsets (UNROLL=8)
//   - ex2-folded gammas: exp(-relu(w*d+b)) = ex2(min(0, fma(-log2e*w, d, -log2e*b)))
//   - sigmoid via 0.5*tanh(0.5v)+0.5 with pre-halved weights (1 MUFU each)
//   - .cs streaming stores (evict-first; keeps L2 clean across graph replays)
// Inputs are [T,B,F] (t-stride BF); output is [B,T,F] (t-stride FF).
// Kernel time ~89us = ~94% of the effective LTS ceiling for this 3R/1W mix.

#define TT 512
#define BB 256
#define FF 256
#define BF (BB * FF)
#define UNROLL 8
#define NBATCH (TT / UNROLL)   // 64
#define BLK 64

__device__ __forceinline__ float tanh_approx(float v) {
    float r;
    asm("tanh.approx.f32 %0, %1;" : "=f"(r) : "f"(v));
    return r;
}
__device__ __forceinline__ float ex2_f(float v) {
    float r;
    asm("ex2.approx.f32 %0, %1;" : "=f"(r) : "f"(v));
    return r;
}

__global__ void __launch_bounds__(BLK) grud_kernel(
    const float* __restrict__ X,
    const float* __restrict__ Mask,
    const float* __restrict__ Delta,
    const float* __restrict__ x_mean,
    const float* __restrict__ w_dg_x, const float* __restrict__ b_dg_x,
    const float* __restrict__ w_dg_h, const float* __restrict__ b_dg_h,
    const float* __restrict__ w_xz,  const float* __restrict__ u_hz, const float* __restrict__ b_z,
    const float* __restrict__ w_xr,  const float* __restrict__ u_hr, const float* __restrict__ b_r,
    const float* __restrict__ w_xh,  const float* __restrict__ u_hh,
    const float* __restrict__ v_mh,  const float* __restrict__ b_h,
    float* __restrict__ out,        // [B, T, F]
    float* __restrict__ out_last)   // [B, F] or nullptr
{
    const int tid = blockIdx.x * BLK + threadIdx.x;
    const int f = tid & (FF - 1);
    const int b = tid >> 8;

    const float LOG2E = 1.4426950408889634f;

    // Per-feature params with constants folded in.
    const float xm    = x_mean[f];
    const float nwdgx = -LOG2E * w_dg_x[f], nbdgx = -LOG2E * b_dg_x[f];
    const float nwdgh = -LOG2E * w_dg_h[f], nbdgh = -LOG2E * b_dg_h[f];
    const float wxz2  = 0.5f * w_xz[f], uhz2 = 0.5f * u_hz[f], bz2 = 0.5f * b_z[f];
    const float wxr2  = 0.5f * w_xr[f], uhr2 = 0.5f * u_hr[f], br2 = 0.5f * b_r[f];
    const float wxh   = w_xh[f], uhh = u_hh[f];
    const float vmh   = v_mh[f], bh  = b_h[f];

    const float* xp = X     + (size_t)b * FF + f;   // [T,B,F]: t-stride = BF
    const float* mp = Mask  + (size_t)b * FF + f;
    const float* dp = Delta + (size_t)b * FF + f;
    float*       op = out   + (size_t)b * TT * FF + f;  // [B,T,F]: t-stride = FF

    float h = 0.0f;

    // 3 register buffers; all slot indices below are literal constants.
    float xv[3][UNROLL], mv[3][UNROLL], dv[3][UNROLL];

    auto load_batch = [&](int n, int s) {
        const float* xq = xp + (size_t)n * (BF * UNROLL);
        const float* mq = mp + (size_t)n * (BF * UNROLL);
        const float* dq = dp + (size_t)n * (BF * UNROLL);
        #pragma unroll
        for (int u = 0; u < UNROLL; ++u) {
            xv[s][u] = __ldcs(xq + u * BF);
            mv[s][u] = __ldcs(mq + u * BF);
            dv[s][u] = __ldcs(dq + u * BF);
        }
    };
    auto compute_batch = [&](int n, int s) {
        float* oq = op + (size_t)n * (FF * UNROLL);   // OUTPUT stride: FF per t
        #pragma unroll
        for (int u = 0; u < UNROLL; ++u) {
            float x = xv[s][u], m = mv[s][u], d = dv[s][u];

            // gamma = exp(-relu(w*d+b)) = ex2(min(0, fma(nw, d, nb)))
            float gx = ex2_f(fminf(0.0f, fmaf(nwdgx, d, nbdgx)));
            float gh = ex2_f(fminf(0.0f, fmaf(nwdgh, d, nbdgh)));

            // x = m*x + (1-m)*(gx*x + (1-gx)*xm)
            float ximp = fmaf(gx, x, (1.0f - gx) * xm);
            x = fmaf(m, x, (1.0f - m) * ximp);

            // h-independent partials (fill load shadow)
            float pz = fmaf(wxz2, x, bz2);
            float pr = fmaf(wxr2, x, br2);
            float ph = fmaf(wxh, x, fmaf(vmh, m, bh));

            h = gh * h;

            float z  = fmaf(0.5f, tanh_approx(fmaf(uhz2, h, pz)), 0.5f);
            float r  = fmaf(0.5f, tanh_approx(fmaf(uhr2, h, pr)), 0.5f);
            float ht = tanh_approx(fmaf(uhh, r * h, ph));

            h = fmaf(z, ht - h, h);

            __stcs(oq + u * FF, h);                   // streaming store
        }
    };

    // Depth-2 pipeline, period-3 slot rotation via x3-unrolled loop.
    load_batch(0, 0);
    load_batch(1, 1);

    #pragma unroll 1
    for (int n = 0; n < NBATCH - 1; n += 3) {
        load_batch(n + 2, 2);
        compute_batch(n, 0);                        // slot0 free
        if (n + 3 < NBATCH) load_batch(n + 3, 0);
        compute_batch(n + 1, 1);                    // slot1 free
        if (n + 4 < NBATCH) load_batch(n + 4, 1);
        compute_batch(n + 2, 2);                    // slot2 free
    }
    // Batch 63 was loaded into slot0 during the n=60 iteration.
    compute_batch(NBATCH - 1, 0);

    if (out_last != nullptr) {
        out_last[(size_t)b * FF + f] = h;
    }
}

extern "C" void kernel_launch(void* const* d_in, const int* in_sizes, int n_in,
                              void* d_out, int out_size) {
    const float* X      = (const float*)d_in[0];
    const float* Mask   = (const float*)d_in[1];
    const float* Delta  = (const float*)d_in[2];
    const float* x_mean = (const float*)d_in[3];
    const float* w_dg_x = (const float*)d_in[4];
    const float* b_dg_x = (const float*)d_in[5];
    const float* w_dg_h = (const float*)d_in[6];
    const float* b_dg_h = (const float*)d_in[7];
    const float* w_xz   = (const float*)d_in[8];
    const float* u_hz   = (const float*)d_in[9];
    const float* b_z    = (const float*)d_in[10];
    const float* w_xr   = (const float*)d_in[11];
    const float* u_hr   = (const float*)d_in[12];
    const float* b_r    = (const float*)d_in[13];
    const float* w_xh   = (const float*)d_in[14];
    const float* u_hh   = (const float*)d_in[15];
    const float* v_mh   = (const float*)d_in[16];
    const float* b_h    = (const float*)d_in[17];

    float* out = (float*)d_out;
    const long long hs_elems = (long long)BB * TT * FF;
    float* out_last = ((long long)out_size >= hs_elems + (long long)BB * FF)
                          ? out + hs_elems : nullptr;

    grud_kernel<<<BF / BLK, BLK>>>(X, Mask, Delta, x_mean,
                                   w_dg_x, b_dg_x, w_dg_h, b_dg_h,
                                   w_xz, u_hz, b_z,
                                   w_xr, u_hr, b_r,
                                   w_xh, u_hh, v_mh, b_h,
                                   out, out_last);
}